// round 1
// baseline (speedup 1.0000x reference)
#include <cuda_runtime.h>
#include <cstdint>

#define N_NODES 262144
#define N_EDGES 524288
#define D 256

// ---------------- scratch (device globals; no allocation allowed) ----------------
__device__ float g_hbuf[(size_t)N_NODES * D];   // current node features
__device__ float g_aggbuf[(size_t)N_NODES * D]; // neighbor sums
__device__ float g_xbuf[(size_t)N_NODES * D];   // pre-LN layer output
__device__ float g_wtbuf[512 * D];              // [k=512][n=256]: concat(Wl^T, Wr^T)

// ---------------- helpers ----------------
__device__ __forceinline__ float to_tf32(float x) {
    float y;
    asm("cvt.rna.tf32.f32 %0, %1;" : "=f"(y) : "f"(x));
    return y;
}

__device__ __forceinline__ void mma_tf32(float* d, const unsigned* a, const unsigned* b) {
    asm volatile(
        "mma.sync.aligned.m16n8k8.row.col.f32.tf32.tf32.f32 "
        "{%0,%1,%2,%3},{%4,%5,%6,%7},{%8,%9},{%0,%1,%2,%3};"
        : "+f"(d[0]), "+f"(d[1]), "+f"(d[2]), "+f"(d[3])
        : "r"(a[0]), "r"(a[1]), "r"(a[2]), "r"(a[3]), "r"(b[0]), "r"(b[1]));
}

// Block-wide LayerNorm stats over 256 values (one value per thread, 256 threads).
__device__ __forceinline__ void block_ln_stats(float v, float* sh, float& mean, float& rstd)
{
    int lane = threadIdx.x & 31;
    int w    = threadIdx.x >> 5;
    float s = v, q = v * v;
#pragma unroll
    for (int o = 16; o; o >>= 1) {
        s += __shfl_xor_sync(0xffffffffu, s, o);
        q += __shfl_xor_sync(0xffffffffu, q, o);
    }
    if (lane == 0) { sh[w] = s; sh[8 + w] = q; }
    __syncthreads();
    if (threadIdx.x == 0) {
        float ts = 0.f, tq = 0.f;
#pragma unroll
        for (int i = 0; i < 8; i++) { ts += sh[i]; tq += sh[8 + i]; }
        float m   = ts * (1.0f / 256.0f);
        float var = tq * (1.0f / 256.0f) - m * m;
        sh[16] = m;
        sh[17] = rsqrtf(var + 1e-5f);
    }
    __syncthreads();
    mean = sh[16];
    rstd = sh[17];
}

// ---------------- kernels ----------------

// h = LN(node_tab[node_emb]*16 + pos_tab[pos]) * g + b
__global__ void embed_ln_kernel(const int* __restrict__ node_emb, const int* __restrict__ pos,
                                const float* __restrict__ node_tab, const float* __restrict__ pos_tab,
                                const float* __restrict__ gw, const float* __restrict__ bw,
                                float* __restrict__ out)
{
    __shared__ float sh[18];
    int row = blockIdx.x;
    int c   = threadIdx.x;
    int ne  = __ldg(node_emb + row);
    int p   = __ldg(pos + row);
    float v = node_tab[(size_t)ne * D + c] * 16.0f + pos_tab[(size_t)p * D + c];
    float m, r;
    block_ln_stats(v, sh, m, r);
    out[(size_t)row * D + c] = (v - m) * r * gw[c] + bw[c];
}

// out = LN(x) * g + b
__global__ void ln_kernel(const float* __restrict__ x,
                          const float* __restrict__ gw, const float* __restrict__ bw,
                          float* __restrict__ out)
{
    __shared__ float sh[18];
    int row = blockIdx.x;
    int c   = threadIdx.x;
    float v = x[(size_t)row * D + c];
    float m, r;
    block_ln_stats(v, sh, m, r);
    out[(size_t)row * D + c] = (v - m) * r * gw[c] + bw[c];
}

__global__ void zero_kernel(float4* __restrict__ p)
{
    size_t i = (size_t)blockIdx.x * blockDim.x + threadIdx.x;
    p[i] = make_float4(0.f, 0.f, 0.f, 0.f);
}

// wt[k][n] = (k<256 ? Wl[n][k] : Wr[n][k-256])
__global__ void build_wt_kernel(const float* __restrict__ Wl, const float* __restrict__ Wr,
                                float* __restrict__ wt)
{
    int k = blockIdx.x;
    int n = threadIdx.x;
    wt[k * D + n] = (k < 256) ? Wl[n * D + k] : Wr[n * D + (k - 256)];
}

// agg[dst] += h[src] for each edge; one warp per edge.
__global__ void scatter_kernel(const int* __restrict__ src, const int* __restrict__ dst,
                               const float* __restrict__ h, float* __restrict__ agg, int nE)
{
    int e = blockIdx.x * 8 + (threadIdx.x >> 5);
    if (e >= nE) return;
    int lane = threadIdx.x & 31;
    int s = __ldg(src + e);
    int d = __ldg(dst + e);
    const float4* hs = (const float4*)(h + (size_t)s * D);
    float4 v0 = hs[lane];
    float4 v1 = hs[lane + 32];
    float* ag = agg + (size_t)d * D;
    int o0 = lane * 4;
    atomicAdd(ag + o0 + 0, v0.x);
    atomicAdd(ag + o0 + 1, v0.y);
    atomicAdd(ag + o0 + 2, v0.z);
    atomicAdd(ag + o0 + 3, v0.w);
    int o1 = 128 + lane * 4;
    atomicAdd(ag + o1 + 0, v1.x);
    atomicAdd(ag + o1 + 1, v1.y);
    atomicAdd(ag + o1 + 2, v1.z);
    atomicAdd(ag + o1 + 3, v1.w);
}

// x = relu(agg@Wl^T + bl + h@Wr^T) + h   (fused GEMM over K=512 concat, tf32 mma)
// Block tile: 64 rows x 256 cols, BK=32. 8 warps in 2x4 (32-row x 64-col warp tiles).
__global__ __launch_bounds__(256, 2)
void gemm_fused_kernel(const float* __restrict__ agg, const float* __restrict__ h,
                       const float* __restrict__ wt, const float* __restrict__ bl,
                       float* __restrict__ xout)
{
    __shared__ float As[64][33];
    __shared__ float Bs[32][260];

    const int tid  = threadIdx.x;
    const int lane = tid & 31;
    const int w    = tid >> 5;
    const int wr   = w & 1;   // 0..1 : 32-row slice
    const int wc   = w >> 1;  // 0..3 : 64-col slice
    const int rowBase = blockIdx.x * 64;

    float acc[2][8][4];
#pragma unroll
    for (int m = 0; m < 2; m++)
#pragma unroll
        for (int n = 0; n < 8; n++)
#pragma unroll
            for (int i = 0; i < 4; i++) acc[m][n][i] = 0.f;

    const int g = lane >> 2;
    const int t = lane & 3;

    for (int k0 = 0; k0 < 512; k0 += 32) {
        // Load A tile (64x32): k<256 from agg, else from h (concat along K)
#pragma unroll
        for (int i = 0; i < 8; i++) {
            int idx = tid + i * 256;
            int r = idx >> 5;
            int c = idx & 31;
            int k = k0 + c;
            float v = (k < 256) ? agg[(size_t)(rowBase + r) * D + k]
                                : h[(size_t)(rowBase + r) * D + (k - 256)];
            As[r][c] = to_tf32(v);
        }
        // Load B tile (32x256) from pre-transposed weights (coalesced)
#pragma unroll
        for (int i = 0; i < 32; i++) {
            Bs[i][tid] = to_tf32(wt[(size_t)(k0 + i) * D + tid]);
        }
        __syncthreads();

#pragma unroll
        for (int ks = 0; ks < 32; ks += 8) {
            unsigned a[2][4], b[8][2];
#pragma unroll
            for (int m = 0; m < 2; m++) {
                int r0 = wr * 32 + m * 16 + g;
                a[m][0] = __float_as_uint(As[r0][ks + t]);
                a[m][1] = __float_as_uint(As[r0 + 8][ks + t]);
                a[m][2] = __float_as_uint(As[r0][ks + t + 4]);
                a[m][3] = __float_as_uint(As[r0 + 8][ks + t + 4]);
            }
#pragma unroll
            for (int n = 0; n < 8; n++) {
                int col = wc * 64 + n * 8 + g;
                b[n][0] = __float_as_uint(Bs[ks + t][col]);
                b[n][1] = __float_as_uint(Bs[ks + t + 4][col]);
            }
#pragma unroll
            for (int m = 0; m < 2; m++)
#pragma unroll
                for (int n = 0; n < 8; n++)
                    mma_tf32(acc[m][n], a[m], b[n]);
        }
        __syncthreads();
    }

    // Epilogue: +bias, relu, +residual(h); write pre-LN x
#pragma unroll
    for (int m = 0; m < 2; m++) {
#pragma unroll
        for (int n = 0; n < 8; n++) {
            int c  = wc * 64 + n * 8 + t * 2;
            int r0 = rowBase + wr * 32 + m * 16 + g;
            int r1 = r0 + 8;
            float b0v = bl[c], b1v = bl[c + 1];
            float2 h0 = *(const float2*)(h + (size_t)r0 * D + c);
            float2 h1 = *(const float2*)(h + (size_t)r1 * D + c);
            float2 o0, o1;
            o0.x = fmaxf(acc[m][n][0] + b0v, 0.f) + h0.x;
            o0.y = fmaxf(acc[m][n][1] + b1v, 0.f) + h0.y;
            o1.x = fmaxf(acc[m][n][2] + b0v, 0.f) + h1.x;
            o1.y = fmaxf(acc[m][n][3] + b1v, 0.f) + h1.y;
            *(float2*)(xout + (size_t)r0 * D + c) = o0;
            *(float2*)(xout + (size_t)r1 * D + c) = o1;
        }
    }
}

// ---------------- launch ----------------
extern "C" void kernel_launch(void* const* d_in, const int* in_sizes, int n_in,
                              void* d_out, int out_size)
{
    const int*   node_emb = (const int*)d_in[0];
    const int*   pos      = (const int*)d_in[1];
    const int*   edge     = (const int*)d_in[2];
    const float* node_tab = (const float*)d_in[3];
    const float* pos_tab  = (const float*)d_in[4];
    const float* g_emb    = (const float*)d_in[5];
    const float* b_emb    = (const float*)d_in[6];
    const float* Wl0 = (const float*)d_in[7];
    const float* bl0 = (const float*)d_in[8];
    const float* Wr0 = (const float*)d_in[9];
    const float* g0  = (const float*)d_in[10];
    const float* b0  = (const float*)d_in[11];
    const float* Wl1 = (const float*)d_in[12];
    const float* bl1 = (const float*)d_in[13];
    const float* Wr1 = (const float*)d_in[14];
    const float* g1  = (const float*)d_in[15];
    const float* b1  = (const float*)d_in[16];
    float* out = (float*)d_out;

    const int nE = in_sizes[2] / 2;
    const int* srcp = edge;
    const int* dstp = edge + nE;

    float *h, *agg, *x, *wt;
    cudaGetSymbolAddress((void**)&h,   g_hbuf);
    cudaGetSymbolAddress((void**)&agg, g_aggbuf);
    cudaGetSymbolAddress((void**)&x,   g_xbuf);
    cudaGetSymbolAddress((void**)&wt,  g_wtbuf);

    const int zeroBlocks    = (N_NODES * D / 4) / 256; // 65536
    const int scatterBlocks = (nE + 7) / 8;
    const int gemmBlocks    = N_NODES / 64;            // 4096

    // Embedding + LN
    embed_ln_kernel<<<N_NODES, 256>>>(node_emb, pos, node_tab, pos_tab, g_emb, b_emb, h);

    // ---- Layer 0 ----
    build_wt_kernel<<<512, 256>>>(Wl0, Wr0, wt);
    zero_kernel<<<zeroBlocks, 256>>>((float4*)agg);
    scatter_kernel<<<scatterBlocks, 256>>>(srcp, dstp, h, agg, nE);
    gemm_fused_kernel<<<gemmBlocks, 256>>>(agg, h, wt, bl0, x);
    ln_kernel<<<N_NODES, 256>>>(x, g0, b0, h);   // h <- LN(x) in place of old h

    // ---- Layer 1 ----
    build_wt_kernel<<<512, 256>>>(Wl1, Wr1, wt);
    zero_kernel<<<zeroBlocks, 256>>>((float4*)agg);
    scatter_kernel<<<scatterBlocks, 256>>>(srcp, dstp, h, agg, nE);
    gemm_fused_kernel<<<gemmBlocks, 256>>>(agg, h, wt, bl1, x);
    ln_kernel<<<N_NODES, 256>>>(x, g1, b1, out); // final output
}

// round 3
// speedup vs baseline: 2.0161x; 2.0161x over previous
#include <cuda_runtime.h>
#include <cstdint>

#define N_NODES 262144
#define D 256

// ---------------- scratch ----------------
__device__ float g_hbuf[(size_t)N_NODES * D];   // embedding output (layer0 input)
__device__ float g_aggbuf[(size_t)N_NODES * D]; // neighbor sums
__device__ float g_xbuf[(size_t)N_NODES * D];   // layer0 output (layer1 input)

// ---------------- helpers ----------------
__device__ __forceinline__ uint32_t smem_u32(const void* p) {
    uint32_t a;
    asm("{ .reg .u64 t; cvta.to.shared.u64 t, %1; cvt.u32.u64 %0, t; }" : "=r"(a) : "l"(p));
    return a;
}

__device__ __forceinline__ void mma_tf32(float* d, const float* a, const float* b) {
    asm volatile(
        "mma.sync.aligned.m16n8k8.row.col.f32.tf32.tf32.f32 "
        "{%0,%1,%2,%3},{%4,%5,%6,%7},{%8,%9},{%0,%1,%2,%3};"
        : "+f"(d[0]), "+f"(d[1]), "+f"(d[2]), "+f"(d[3])
        : "r"(__float_as_uint(a[0])), "r"(__float_as_uint(a[1])),
          "r"(__float_as_uint(a[2])), "r"(__float_as_uint(a[3])),
          "r"(__float_as_uint(b[0])), "r"(__float_as_uint(b[1])));
}

#define CP_ASYNC16(dst, src) \
    asm volatile("cp.async.cg.shared.global [%0], [%1], 16;" :: "r"(dst), "l"(src))

// ---------------- small kernels ----------------
__device__ __forceinline__ void block_ln_stats(float v, float* sh, float& mean, float& rstd)
{
    int lane = threadIdx.x & 31;
    int w    = threadIdx.x >> 5;
    float s = v, q = v * v;
#pragma unroll
    for (int o = 16; o; o >>= 1) {
        s += __shfl_xor_sync(0xffffffffu, s, o);
        q += __shfl_xor_sync(0xffffffffu, q, o);
    }
    if (lane == 0) { sh[w] = s; sh[8 + w] = q; }
    __syncthreads();
    if (threadIdx.x == 0) {
        float ts = 0.f, tq = 0.f;
#pragma unroll
        for (int i = 0; i < 8; i++) { ts += sh[i]; tq += sh[8 + i]; }
        float m   = ts * (1.0f / 256.0f);
        float var = tq * (1.0f / 256.0f) - m * m;
        sh[16] = m;
        sh[17] = rsqrtf(var + 1e-5f);
    }
    __syncthreads();
    mean = sh[16];
    rstd = sh[17];
}

__global__ void embed_ln_kernel(const int* __restrict__ node_emb, const int* __restrict__ pos,
                                const float* __restrict__ node_tab, const float* __restrict__ pos_tab,
                                const float* __restrict__ gw, const float* __restrict__ bw,
                                float* __restrict__ out)
{
    __shared__ float sh[18];
    int row = blockIdx.x;
    int c   = threadIdx.x;
    int ne  = __ldg(node_emb + row);
    int p   = __ldg(pos + row);
    float v = node_tab[(size_t)ne * D + c] * 16.0f + pos_tab[(size_t)p * D + c];
    float m, r;
    block_ln_stats(v, sh, m, r);
    out[(size_t)row * D + c] = (v - m) * r * gw[c] + bw[c];
}

// agg[dst] += h[src]; one warp/edge, vector reds
__global__ void scatter_kernel(const int* __restrict__ src, const int* __restrict__ dst,
                               const float* __restrict__ h, float* __restrict__ agg, int nE)
{
    int e = blockIdx.x * 8 + (threadIdx.x >> 5);
    if (e >= nE) return;
    int lane = threadIdx.x & 31;
    int s = __ldg(src + e);
    int d = __ldg(dst + e);
    const float4* hs = (const float4*)(h + (size_t)s * D);
    float4 v0 = hs[lane];
    float4 v1 = hs[lane + 32];
    float* ag = agg + (size_t)d * D;
    asm volatile("red.global.add.v4.f32 [%0], {%1,%2,%3,%4};"
                 :: "l"(ag + lane * 4), "f"(v0.x), "f"(v0.y), "f"(v0.z), "f"(v0.w) : "memory");
    asm volatile("red.global.add.v4.f32 [%0], {%1,%2,%3,%4};"
                 :: "l"(ag + 128 + lane * 4), "f"(v1.x), "f"(v1.y), "f"(v1.z), "f"(v1.w) : "memory");
}

// ---------------- fused tf32 GEMM + bias/relu/residual/LN ----------------
// out = LN(relu(agg@Wl^T + bl + h@Wr^T) + h) * g + b
// CTA: 128 rows x 256 cols, K=512 over 16 stages of 32.
// 8 warps (2 row-groups x 4 col-groups), warp tile 64x64 (m4 n8).
// Swizzled smem: float4-granule g' = q ^ (row&7)  -> conflict-free LDS & STS.

#define OFF_BIAS 0
#define OFF_G    1024
#define OFF_B    2048
#define OFF_SUM  3072
#define OFF_SQ   5120
#define OFF_A0   8192
#define OFF_A1   24576
#define OFF_B0   40960
#define OFF_B1   73728
#define SMEM_BYTES 106496

__global__ __launch_bounds__(256, 1)
void gemm_ln_kernel(const float* __restrict__ agg, const float* __restrict__ h,
                    const float* __restrict__ Wl, const float* __restrict__ Wr,
                    const float* __restrict__ bl, const float* __restrict__ gw,
                    const float* __restrict__ bw, float* __restrict__ out)
{
    extern __shared__ char smem[];
    const uint32_t sb = smem_u32(smem);
    const int tid  = threadIdx.x;
    const int w    = tid >> 5;
    const int lane = tid & 31;
    const int g    = lane >> 2;
    const int t    = lane & 3;
    const int wr   = w & 1;   // row group (64 rows)
    const int wc   = w >> 1;  // col group (64 cols)
    const int rowBase = blockIdx.x * 128;

    float* biasS = (float*)(smem + OFF_BIAS);
    float* gS    = (float*)(smem + OFF_G);
    float* bS    = (float*)(smem + OFF_B);
    float* sumP  = (float*)(smem + OFF_SUM);   // [128][4]
    float* sqP   = (float*)(smem + OFF_SQ);    // [128][4]

    biasS[tid] = bl[tid];
    gS[tid]    = gw[tid];
    bS[tid]    = bw[tid];

    float acc[4][8][4];
#pragma unroll
    for (int i = 0; i < 4; i++)
#pragma unroll
        for (int j = 0; j < 8; j++)
#pragma unroll
            for (int q = 0; q < 4; q++) acc[i][j][q] = 0.f;

    // ---- software pipeline: 16 stages of K=32 ----
    // stage s: A = (s<8 ? agg : h) rows [rowBase,+128), k = (s&7)*32
    //          B = (s<8 ? Wl : Wr) rows [0,256), k same
    auto issue_load = [&](int s) {
        const float* A_ = (s < 8) ? agg : h;
        const float* B_ = (s < 8) ? Wl : Wr;
        const int k0 = (s & 7) * 32;
        const uint32_t aB = sb + OFF_A0 + (s & 1) * 16384;
        const uint32_t bB = sb + OFF_B0 + (s & 1) * 32768;
#pragma unroll
        for (int it = 0; it < 4; it++) {            // 1024 float4s
            int idx = tid + it * 256;
            int r = idx >> 3, q = idx & 7;
            const float* src = A_ + (size_t)(rowBase + r) * D + k0 + q * 4;
            CP_ASYNC16(aB + r * 128 + ((q ^ (r & 7)) << 4), src);
        }
#pragma unroll
        for (int it = 0; it < 8; it++) {            // 2048 float4s
            int idx = tid + it * 256;
            int n = idx >> 3, q = idx & 7;
            const float* src = B_ + (size_t)n * D + k0 + q * 4;
            CP_ASYNC16(bB + n * 128 + ((q ^ (n & 7)) << 4), src);
        }
        asm volatile("cp.async.commit_group;");
    };

    issue_load(0);

    const int t4 = t * 4;
    const uint32_t aRow = (wr * 64 + g) * 128;   // byte offset of row (i=0)
    const uint32_t bCol = (wc * 64 + g) * 128;   // byte offset of col (j=0)

    for (int s = 0; s < 16; s++) {
        if (s < 15) {
            issue_load(s + 1);
            asm volatile("cp.async.wait_group 1;" ::: "memory");
        } else {
            asm volatile("cp.async.wait_group 0;" ::: "memory");
        }
        __syncthreads();

        const char* sA = smem + OFF_A0 + (s & 1) * 16384;
        const char* sB = smem + OFF_B0 + (s & 1) * 32768;

#pragma unroll
        for (int kk = 0; kk < 32; kk += 8) {
            const int q0 = kk >> 2;
            const uint32_t off0 = (((q0 ^ g) << 4) | t4);
            const uint32_t off1 = ((((q0 + 1) ^ g) << 4) | t4);
            float a[4][4], b[8][2];
#pragma unroll
            for (int i = 0; i < 4; i++) {
                const char* p = sA + aRow + i * 2048;
                a[i][0] = *(const float*)(p + off0);
                a[i][1] = *(const float*)(p + 1024 + off0);
                a[i][2] = *(const float*)(p + off1);
                a[i][3] = *(const float*)(p + 1024 + off1);
            }
#pragma unroll
            for (int j = 0; j < 8; j++) {
                const char* p = sB + bCol + j * 1024;
                b[j][0] = *(const float*)(p + off0);
                b[j][1] = *(const float*)(p + off1);
            }
#pragma unroll
            for (int i = 0; i < 4; i++)
#pragma unroll
                for (int j = 0; j < 8; j++)
                    mma_tf32(acc[i][j], a[i], b[j]);
        }
        __syncthreads();
    }

    // ---- epilogue: v = relu(acc + bias) + h ; LN over 256 cols ----
    float s0[4], q0s[4], s1[4], q1s[4];
#pragma unroll
    for (int i = 0; i < 4; i++) {
        s0[i] = 0.f; q0s[i] = 0.f; s1[i] = 0.f; q1s[i] = 0.f;
        const int row0 = rowBase + wr * 64 + i * 16 + g;
#pragma unroll
        for (int j = 0; j < 8; j++) {
            const int c = wc * 64 + j * 8 + t * 2;
            const float b0 = biasS[c], b1 = biasS[c + 1];
            float2 h0 = *(const float2*)(h + (size_t)row0 * D + c);
            float2 h1 = *(const float2*)(h + (size_t)(row0 + 8) * D + c);
            float v0 = fmaxf(acc[i][j][0] + b0, 0.f) + h0.x;
            float v1 = fmaxf(acc[i][j][1] + b1, 0.f) + h0.y;
            float v2 = fmaxf(acc[i][j][2] + b0, 0.f) + h1.x;
            float v3 = fmaxf(acc[i][j][3] + b1, 0.f) + h1.y;
            acc[i][j][0] = v0; acc[i][j][1] = v1; acc[i][j][2] = v2; acc[i][j][3] = v3;
            s0[i] += v0 + v1;  q0s[i] += v0 * v0 + v1 * v1;
            s1[i] += v2 + v3;  q1s[i] += v2 * v2 + v3 * v3;
        }
    }
    // reduce over the 4 t-lanes (lanes g*4 + t)
#pragma unroll
    for (int i = 0; i < 4; i++) {
#pragma unroll
        for (int o = 1; o <= 2; o <<= 1) {
            s0[i]  += __shfl_xor_sync(0xffffffffu, s0[i], o);
            q0s[i] += __shfl_xor_sync(0xffffffffu, q0s[i], o);
            s1[i]  += __shfl_xor_sync(0xffffffffu, s1[i], o);
            q1s[i] += __shfl_xor_sync(0xffffffffu, q1s[i], o);
        }
    }
    if (t == 0) {
#pragma unroll
        for (int i = 0; i < 4; i++) {
            const int r0 = wr * 64 + i * 16 + g;
            sumP[r0 * 4 + wc] = s0[i];       sqP[r0 * 4 + wc] = q0s[i];
            sumP[(r0 + 8) * 4 + wc] = s1[i]; sqP[(r0 + 8) * 4 + wc] = q1s[i];
        }
    }
    __syncthreads();

#pragma unroll
    for (int i = 0; i < 4; i++) {
        const int r0 = wr * 64 + i * 16 + g;
        float4 sp0 = *(const float4*)(sumP + r0 * 4);
        float4 qp0 = *(const float4*)(sqP + r0 * 4);
        float4 sp1 = *(const float4*)(sumP + (r0 + 8) * 4);
        float4 qp1 = *(const float4*)(sqP + (r0 + 8) * 4);
        float m0 = (sp0.x + sp0.y + sp0.z + sp0.w) * (1.0f / 256.0f);
        float m1 = (sp1.x + sp1.y + sp1.z + sp1.w) * (1.0f / 256.0f);
        float r0v = rsqrtf((qp0.x + qp0.y + qp0.z + qp0.w) * (1.0f / 256.0f) - m0 * m0 + 1e-5f);
        float r1v = rsqrtf((qp1.x + qp1.y + qp1.z + qp1.w) * (1.0f / 256.0f) - m1 * m1 + 1e-5f);
        const size_t gr0 = (size_t)(rowBase + r0) * D;
        const size_t gr1 = gr0 + 8 * D;
#pragma unroll
        for (int j = 0; j < 8; j++) {
            const int c = wc * 64 + j * 8 + t * 2;
            const float gg0 = gS[c], gg1 = gS[c + 1];
            const float bb0 = bS[c], bb1 = bS[c + 1];
            float2 o0, o1;
            o0.x = (acc[i][j][0] - m0) * r0v * gg0 + bb0;
            o0.y = (acc[i][j][1] - m0) * r0v * gg1 + bb1;
            o1.x = (acc[i][j][2] - m1) * r1v * gg0 + bb0;
            o1.y = (acc[i][j][3] - m1) * r1v * gg1 + bb1;
            *(float2*)(out + gr0 + c) = o0;
            *(float2*)(out + gr1 + c) = o1;
        }
    }
}

// ---------------- launch ----------------
extern "C" void kernel_launch(void* const* d_in, const int* in_sizes, int n_in,
                              void* d_out, int out_size)
{
    const int*   node_emb = (const int*)d_in[0];
    const int*   pos      = (const int*)d_in[1];
    const int*   edge     = (const int*)d_in[2];
    const float* node_tab = (const float*)d_in[3];
    const float* pos_tab  = (const float*)d_in[4];
    const float* g_emb    = (const float*)d_in[5];
    const float* b_emb    = (const float*)d_in[6];
    const float* Wl0 = (const float*)d_in[7];
    const float* bl0 = (const float*)d_in[8];
    const float* Wr0 = (const float*)d_in[9];
    const float* g0  = (const float*)d_in[10];
    const float* b0  = (const float*)d_in[11];
    const float* Wl1 = (const float*)d_in[12];
    const float* bl1 = (const float*)d_in[13];
    const float* Wr1 = (const float*)d_in[14];
    const float* g1  = (const float*)d_in[15];
    const float* b1  = (const float*)d_in[16];
    float* out = (float*)d_out;

    const int nE = in_sizes[2] / 2;
    const int* srcp = edge;
    const int* dstp = edge + nE;

    float *h, *agg, *x;
    cudaGetSymbolAddress((void**)&h,   g_hbuf);
    cudaGetSymbolAddress((void**)&agg, g_aggbuf);
    cudaGetSymbolAddress((void**)&x,   g_xbuf);

    cudaFuncSetAttribute(gemm_ln_kernel, cudaFuncAttributeMaxDynamicSharedMemorySize, SMEM_BYTES);

    const int scatterBlocks = (nE + 7) / 8;
    const int gemmBlocks    = N_NODES / 128;  // 2048
    const size_t aggBytes   = (size_t)N_NODES * D * sizeof(float);

    embed_ln_kernel<<<N_NODES, 256>>>(node_emb, pos, node_tab, pos_tab, g_emb, b_emb, h);

    // Layer 0: h -> x
    cudaMemsetAsync(agg, 0, aggBytes);
    scatter_kernel<<<scatterBlocks, 256>>>(srcp, dstp, h, agg, nE);
    gemm_ln_kernel<<<gemmBlocks, 256, SMEM_BYTES>>>(agg, h, Wl0, Wr0, bl0, g0, b0, x);

    // Layer 1: x -> out
    cudaMemsetAsync(agg, 0, aggBytes);
    scatter_kernel<<<scatterBlocks, 256>>>(srcp, dstp, x, agg, nE);
    gemm_ln_kernel<<<gemmBlocks, 256, SMEM_BYTES>>>(agg, x, Wl1, Wr1, bl1, g1, b1, out);
}